// round 1
// baseline (speedup 1.0000x reference)
#include <cuda_runtime.h>
#include <math.h>

#define BB 8
#define XX 128
#define YY 128
#define WW 24
#define DD 4
#define YHH 65
#define NPIX (BB*XX*YY)        // 131072
#define NROWS (BB*XX)          // 1024
#define NFREQ (XX*YHH)         // 8320
#define IOSZ (WW*WW)           // 576

// ---------------- device scratch (static: no allocations allowed) ------------
__device__ float  d_h[(size_t)NPIX*WW];             // (B,X,Y,W)      12.6 MB
__device__ float2 d_hf[(size_t)NROWS*YHH*WW];       // (B,X,YH,W)     12.8 MB
__device__ float2 d_spec[(size_t)NROWS*YHH*WW];     // (B,X,YH,W)     12.8 MB
__device__ float2 d_wt[(size_t)DD*NFREQ*IOSZ];      // (D,f,i,o)     153.4 MB
__device__ float2 d_tw[128];                        // exp(-i*pi*k/64)

__device__ __forceinline__ float2 cmulf(float2 a, float2 b) {
    return make_float2(a.x*b.x - a.y*b.y, a.x*b.y + a.y*b.x);
}

// ---------------- twiddle table ----------------------------------------------
__global__ void k_twiddle() {
    int k = threadIdx.x;   // 0..127
    double s, c;
    sincospi(-(double)k / 64.0, &s, &c);   // angle = -2*pi*k/128
    d_tw[k] = make_float2((float)c, (float)s);
}

// ---------------- weight transpose: (d, io, f) -> (d, f, io) ------------------
// src complex layout: [(d*576 + io)*8320 + f], dst: [(d*8320 + f)*576 + io]
__global__ void k_transpose(const float2* __restrict__ src) {
    __shared__ float2 tile[32][33];
    int dd  = blockIdx.z;
    int f0  = blockIdx.x * 32;
    int io0 = blockIdx.y * 32;
    const float2* s = src + (size_t)dd * IOSZ * NFREQ;
    #pragma unroll
    for (int j = 0; j < 4; j++) {
        int io = io0 + threadIdx.y + j*8;
        int f  = f0 + threadIdx.x;
        tile[threadIdx.y + j*8][threadIdx.x] = s[(size_t)io * NFREQ + f];
    }
    __syncthreads();
    float2* dst = d_wt + (size_t)dd * NFREQ * IOSZ;
    #pragma unroll
    for (int j = 0; j < 4; j++) {
        int f  = f0 + threadIdx.y + j*8;
        int io = io0 + threadIdx.x;
        dst[(size_t)f * IOSZ + io] = tile[threadIdx.x][threadIdx.y + j*8];
    }
}

// ---------------- 128-point Stockham FFT, radix-4 x3 + radix-2 ----------------
// L lines interleaved, layout buf[point*L + line]. blockDim must be 256.
// Result ends in p0 (returned pointer). Ends with __syncthreads().
template<int L, bool INV>
__device__ __forceinline__ float2* fft128r4(float2* p0, float2* p1, int tid,
                                            const float2* __restrict__ tw) {
    float2* src = p0; float2* dst = p1;
    #pragma unroll
    for (int st = 0; st < 3; st++) {
        const int s = 1 << (2*st);            // 1,4,16
        const int m = 32 >> (2*st);           // 32,8,2  (n/4)
        for (int idx = tid; idx < 32*L; idx += 256) {
            int line = idx % L;
            int bf   = idx / L;
            int q = bf & (s - 1);
            int p = bf >> (2*st);
            int base = q + s*p;
            float2 a = src[ base          *L + line];
            float2 b = src[(base +   s*m)*L + line];
            float2 c = src[(base + 2*s*m)*L + line];
            float2 d = src[(base + 3*s*m)*L + line];
            float2 w1 = tw[p*s], w2 = tw[2*p*s], w3 = tw[3*p*s];
            if (INV) { w1.y = -w1.y; w2.y = -w2.y; w3.y = -w3.y; }
            float2 apc = make_float2(a.x+c.x, a.y+c.y);
            float2 amc = make_float2(a.x-c.x, a.y-c.y);
            float2 bpd = make_float2(b.x+d.x, b.y+d.y);
            float2 bmd = make_float2(b.x-d.x, b.y-d.y);
            float2 jb  = INV ? make_float2( bmd.y, -bmd.x)
                             : make_float2(-bmd.y,  bmd.x);
            int ob = q + 4*s*p;
            dst[ ob        *L + line] = make_float2(apc.x+bpd.x, apc.y+bpd.y);
            dst[(ob +   s)*L + line] = cmulf(w1, make_float2(amc.x-jb.x, amc.y-jb.y));
            dst[(ob + 2*s)*L + line] = cmulf(w2, make_float2(apc.x-bpd.x, apc.y-bpd.y));
            dst[(ob + 3*s)*L + line] = cmulf(w3, make_float2(amc.x+jb.x, amc.y+jb.y));
        }
        __syncthreads();
        float2* t = src; src = dst; dst = t;
    }
    // final radix-2: n=2, s=64, twiddle = 1
    for (int idx = tid; idx < 64*L; idx += 256) {
        int line = idx % L;
        int q    = idx / L;
        float2 a = src[ q      *L + line];
        float2 b = src[(q + 64)*L + line];
        dst[ q      *L + line] = make_float2(a.x+b.x, a.y+b.y);
        dst[(q + 64)*L + line] = make_float2(a.x-b.x, a.y-b.y);
    }
    __syncthreads();
    return dst;   // == p0 after 3 swaps
}

// ---------------- in mapping: h0 = x @ in_w + in_b ----------------------------
__global__ void k_inmap(const float* __restrict__ x,
                        const float* __restrict__ iw,
                        const float* __restrict__ ib) {
    int p = blockIdx.x * blockDim.x + threadIdx.x;
    if (p >= NPIX) return;
    float a = x[2*p], b = x[2*p + 1];
    float* out = d_h + (size_t)p * WW;
    #pragma unroll
    for (int w = 0; w < WW; w++)
        out[w] = a*iw[w] + b*iw[WW + w] + ib[w];
}

// ---------------- rfft along y per (b,x) row (run once at start) --------------
__global__ void k_rfft_y() {
    extern __shared__ float2 sm[];
    float2* bufA = sm;
    float2* bufB = sm + 128*WW;
    __shared__ float2 tw[128];
    int tid = threadIdx.x;
    if (tid < 128) tw[tid] = d_tw[tid];
    int row = blockIdx.x;
    const float* hsrc = d_h + (size_t)row * YY * WW;
    for (int i = tid; i < YY*WW; i += 256) bufA[i] = make_float2(hsrc[i], 0.0f);
    __syncthreads();
    float2* R = fft128r4<WW,false>(bufA, bufB, tid, tw);
    float2* outhf = d_hf + (size_t)row * YHH * WW;
    for (int i = tid; i < YHH*WW; i += 256) outhf[i] = R[i];
}

// ---------------- fused fft-x + spectral matmul + ifft-x ----------------------
// block = (yh, batch-half of 4). L = 4*24 = 96 lines, smem = 2*128*96*8 = 192KB
__global__ void k_spectral(int layer) {
    extern __shared__ float2 sm[];
    float2* bufA = sm;
    float2* bufB = sm + 128*96;
    __shared__ float2 tw[128];
    int tid = threadIdx.x;
    if (tid < 128) tw[tid] = d_tw[tid];
    int yh = blockIdx.x % YHH;
    int b0 = (blockIdx.x / YHH) * 4;

    for (int idx = tid; idx < 128*96; idx += 256) {
        int x = idx / 96, l = idx % 96;
        int b = b0 + l / WW, i = l % WW;
        bufA[idx] = d_hf[(((size_t)b*XX + x)*YHH + yh)*WW + i];
    }
    __syncthreads();

    float2* F = fft128r4<96,false>(bufA, bufB, tid, tw);     // = bufA
    float2* G = (F == bufA) ? bufB : bufA;

    // yf[b][o] = sum_i hf[b][i] * w[i][o]; 4 batches per weight load
    const float2* wt = d_wt + (size_t)layer * NFREQ * IOSZ;
    for (int j = tid; j < 128*WW; j += 256) {
        int x = j / WW, o = j % WW;
        const float2* wp  = wt + ((size_t)x*YHH + yh)*IOSZ + o;
        const float2* hp  = F + x*96;
        float2 a0 = {0,0}, a1 = {0,0}, a2 = {0,0}, a3 = {0,0};
        #pragma unroll
        for (int i = 0; i < WW; i++) {
            float2 w = __ldg(wp + i*WW);
            float2 h0 = hp[i], h1 = hp[24+i], h2 = hp[48+i], h3 = hp[72+i];
            a0.x += h0.x*w.x - h0.y*w.y;  a0.y += h0.x*w.y + h0.y*w.x;
            a1.x += h1.x*w.x - h1.y*w.y;  a1.y += h1.x*w.y + h1.y*w.x;
            a2.x += h2.x*w.x - h2.y*w.y;  a2.y += h2.x*w.y + h2.y*w.x;
            a3.x += h3.x*w.x - h3.y*w.y;  a3.y += h3.x*w.y + h3.y*w.x;
        }
        G[x*96      + o] = a0;
        G[x*96 + 24 + o] = a1;
        G[x*96 + 48 + o] = a2;
        G[x*96 + 72 + o] = a3;
    }
    __syncthreads();

    float2* S = fft128r4<96,true>(G, F, tid, tw);            // = G

    for (int idx = tid; idx < 128*96; idx += 256) {
        int x = idx / 96, l = idx % 96;
        int b = b0 + l / WW, i = l % WW;
        d_spec[(((size_t)b*XX + x)*YHH + yh)*WW + i] = S[idx];
    }
}

// ---------------- fused irfft-y + 1x1 conv + relu (+ out-map) (+ next rfft-y) -
__global__ void k_update(int layer, int t, int Trt, int flags,
                         const float* __restrict__ conv_w,
                         const float* __restrict__ conv_b,
                         const float* __restrict__ out_w,
                         const float* __restrict__ out_b,
                         float* __restrict__ outp) {
    extern __shared__ float2 sm[];
    float2* bufA = sm;
    float2* bufB = sm + 128*WW;
    __shared__ float2 tw[128];
    int tid = threadIdx.x;
    if (tid < 128) tw[tid] = d_tw[tid];
    int row = blockIdx.x;                 // b*128 + x

    // load half-spectrum (65 bins), Hermitian-extend to 128
    const float2* spec = d_spec + (size_t)row * YHH * WW;
    for (int i = tid; i < YHH*WW; i += 256) bufA[i] = spec[i];
    __syncthreads();
    for (int idx = tid; idx < 63*WW; idx += 256) {
        int p = 65 + idx / WW, ch = idx % WW;
        float2 v = bufA[(128 - p)*WW + ch];
        bufA[p*WW + ch] = make_float2(v.x, -v.y);
    }
    __syncthreads();

    float2* R = fft128r4<WW,true>(bufA, bufB, tid, tw);   // = bufA (x1*16384 complex)
    float*  hrow = (float*)((R == bufA) ? bufB : bufA);

    const float* hsrc = d_h + (size_t)row * YY * WW;
    for (int i = tid; i < YY*WW; i += 256) hrow[i] = hsrc[i];
    __syncthreads();

    const float* cw = conv_w + layer * IOSZ;
    const float* cb = conv_b + layer * WW;
    float* hdst = d_h + (size_t)row * YY * WW;
    for (int idx = tid; idx < YY*WW; idx += 256) {
        int y = idx / WW, o = idx % WW;
        float x1 = R[idx].x * (1.0f/16384.0f);
        float acc = cb[o];
        const float* hr = hrow + y*WW;
        #pragma unroll
        for (int i = 0; i < WW; i++) acc += hr[i] * __ldg(cw + i*WW + o);
        float hn = fmaxf(x1, 0.0f) + acc;
        hdst[idx] = hn;
        R[idx] = make_float2(hn, 0.0f);
    }
    __syncthreads();

    if (flags & 1) {   // out mapping for this timestep (COUT = 1)
        int b = row >> 7, xs = row & 127;
        float ob0 = out_b[0];
        for (int y = tid; y < YY; y += 256) {
            float s = ob0;
            #pragma unroll
            for (int o = 0; o < WW; o++) s += R[y*WW + o].x * __ldg(out_w + o);
            outp[(((size_t)b*Trt + t)*XX + xs)*YY + y] = s;
        }
    }

    if (flags & 2) {   // rfft-y of h_new for the next layer/timestep
        float2* other = (R == bufA) ? bufB : bufA;
        float2* HF = fft128r4<WW,false>(R, other, tid, tw);   // = R
        float2* outhf = d_hf + (size_t)row * YHH * WW;
        for (int i = tid; i < YHH*WW; i += 256) outhf[i] = HF[i];
    }
}

// ---------------- host launcher ----------------------------------------------
extern "C" void kernel_launch(void* const* d_in, const int* in_sizes, int n_in,
                              void* d_out, int out_size) {
    const float* x      = (const float*)d_in[0];
    const float* in_w   = (const float*)d_in[1];
    const float* in_b   = (const float*)d_in[2];
    const float* spec_w = (const float*)d_in[3];
    const float* conv_w = (const float*)d_in[4];
    const float* conv_b = (const float*)d_in[5];
    const float* out_w  = (const float*)d_in[6];
    const float* out_b  = (const float*)d_in[7];
    float* outp = (float*)d_out;
    int Trt = out_size / (BB * XX * YY);

    const int SMEM_ROW  = 2 * 128 * WW * (int)sizeof(float2);   // 49152
    const int SMEM_SPEC = 2 * 128 * 96 * (int)sizeof(float2);   // 196608
    cudaFuncSetAttribute(k_spectral, cudaFuncAttributeMaxDynamicSharedMemorySize, SMEM_SPEC);
    cudaFuncSetAttribute(k_rfft_y,   cudaFuncAttributeMaxDynamicSharedMemorySize, SMEM_ROW);
    cudaFuncSetAttribute(k_update,   cudaFuncAttributeMaxDynamicSharedMemorySize, SMEM_ROW);

    k_twiddle<<<1, 128>>>();

    dim3 tb(32, 8), tg(NFREQ/32, IOSZ/32, DD);                  // (260,18,4)
    k_transpose<<<tg, tb>>>((const float2*)spec_w);

    k_inmap<<<(NPIX + 255)/256, 256>>>(x, in_w, in_b);
    k_rfft_y<<<NROWS, 256, SMEM_ROW>>>();

    for (int t = 0; t < Trt; t++) {
        for (int d = 0; d < DD; d++) {
            k_spectral<<<2*YHH, 256, SMEM_SPEC>>>(d);
            int flags = (d == DD-1 ? 1 : 0)
                      | ((t == Trt-1 && d == DD-1) ? 0 : 2);
            k_update<<<NROWS, 256, SMEM_ROW>>>(d, t, Trt, flags,
                                               conv_w, conv_b, out_w, out_b, outp);
        }
    }
}

// round 2
// speedup vs baseline: 1.2734x; 1.2734x over previous
#include <cuda_runtime.h>
#include <math.h>

#define BB 8
#define XX 128
#define YY 128
#define WW 24
#define DD 4
#define YHH 65
#define NPIX (BB*XX*YY)        // 131072
#define NROWS (BB*XX)          // 1024
#define NFREQ (XX*YHH)         // 8320
#define IOSZ (WW*WW)           // 576

// ---------------- device scratch (static: no allocations allowed) ------------
__device__ float  d_h[(size_t)NPIX*WW];             // (B,X,Y,W)      12.6 MB
__device__ float2 d_hf[(size_t)NROWS*YHH*WW];       // (B,X,YH,W)     12.8 MB
__device__ float2 d_spec[(size_t)NROWS*YHH*WW];     // (B,X,YH,W)     12.8 MB
__device__ float2 d_wt[(size_t)DD*NFREQ*IOSZ];      // (D,f,i,o)     153.4 MB
__device__ float2 d_tw[128];                        // exp(-i*pi*k/64)

__device__ __forceinline__ float2 cmulf(float2 a, float2 b) {
    return make_float2(a.x*b.x - a.y*b.y, a.x*b.y + a.y*b.x);
}

// ---------------- twiddle table ----------------------------------------------
__global__ void k_twiddle() {
    int k = threadIdx.x;   // 0..127
    double s, c;
    sincospi(-(double)k / 64.0, &s, &c);   // angle = -2*pi*k/128
    d_tw[k] = make_float2((float)c, (float)s);
}

// ---------------- weight transpose: (d, io, f) -> (d, f, io) ------------------
__global__ void k_transpose(const float2* __restrict__ src) {
    __shared__ float2 tile[32][33];
    int dd  = blockIdx.z;
    int f0  = blockIdx.x * 32;
    int io0 = blockIdx.y * 32;
    const float2* s = src + (size_t)dd * IOSZ * NFREQ;
    #pragma unroll
    for (int j = 0; j < 4; j++) {
        int io = io0 + threadIdx.y + j*8;
        int f  = f0 + threadIdx.x;
        tile[threadIdx.y + j*8][threadIdx.x] = s[(size_t)io * NFREQ + f];
    }
    __syncthreads();
    float2* dst = d_wt + (size_t)dd * NFREQ * IOSZ;
    #pragma unroll
    for (int j = 0; j < 4; j++) {
        int f  = f0 + threadIdx.y + j*8;
        int io = io0 + threadIdx.x;
        dst[(size_t)f * IOSZ + io] = tile[threadIdx.x][threadIdx.y + j*8];
    }
}

// ---------------- 128-point Stockham FFT, radix-4 x3 + radix-2 ----------------
// L lines interleaved, layout buf[point*L + line]. NT = blockDim.x.
// Result ends in p0 (returned pointer). Ends with __syncthreads().
template<int L, bool INV, int NT>
__device__ __forceinline__ float2* fft128r4(float2* p0, float2* p1, int tid,
                                            const float2* __restrict__ tw) {
    float2* src = p0; float2* dst = p1;
    #pragma unroll
    for (int st = 0; st < 3; st++) {
        const int s = 1 << (2*st);            // 1,4,16
        const int m = 32 >> (2*st);           // 32,8,2  (n/4)
        #pragma unroll 2
        for (int idx = tid; idx < 32*L; idx += NT) {
            int line = idx % L;
            int bf   = idx / L;
            int q = bf & (s - 1);
            int p = bf >> (2*st);
            int base = q + s*p;
            float2 a = src[ base          *L + line];
            float2 b = src[(base +   s*m)*L + line];
            float2 c = src[(base + 2*s*m)*L + line];
            float2 d = src[(base + 3*s*m)*L + line];
            float2 w1 = tw[p*s], w2 = tw[2*p*s], w3 = tw[3*p*s];
            if (INV) { w1.y = -w1.y; w2.y = -w2.y; w3.y = -w3.y; }
            float2 apc = make_float2(a.x+c.x, a.y+c.y);
            float2 amc = make_float2(a.x-c.x, a.y-c.y);
            float2 bpd = make_float2(b.x+d.x, b.y+d.y);
            float2 bmd = make_float2(b.x-d.x, b.y-d.y);
            float2 jb  = INV ? make_float2( bmd.y, -bmd.x)
                             : make_float2(-bmd.y,  bmd.x);
            int ob = q + 4*s*p;
            dst[ ob        *L + line] = make_float2(apc.x+bpd.x, apc.y+bpd.y);
            dst[(ob +   s)*L + line] = cmulf(w1, make_float2(amc.x-jb.x, amc.y-jb.y));
            dst[(ob + 2*s)*L + line] = cmulf(w2, make_float2(apc.x-bpd.x, apc.y-bpd.y));
            dst[(ob + 3*s)*L + line] = cmulf(w3, make_float2(amc.x+jb.x, amc.y+jb.y));
        }
        __syncthreads();
        float2* t = src; src = dst; dst = t;
    }
    // final radix-2: n=2, s=64, twiddle = 1
    #pragma unroll 2
    for (int idx = tid; idx < 64*L; idx += NT) {
        int line = idx % L;
        int q    = idx / L;
        float2 a = src[ q      *L + line];
        float2 b = src[(q + 64)*L + line];
        dst[ q      *L + line] = make_float2(a.x+b.x, a.y+b.y);
        dst[(q + 64)*L + line] = make_float2(a.x-b.x, a.y-b.y);
    }
    __syncthreads();
    return dst;   // == p0
}

// ---------------- in mapping: h0 = x @ in_w + in_b ----------------------------
__global__ void k_inmap(const float* __restrict__ x,
                        const float* __restrict__ iw,
                        const float* __restrict__ ib) {
    int p = blockIdx.x * blockDim.x + threadIdx.x;
    if (p >= NPIX) return;
    float a = x[2*p], b = x[2*p + 1];
    float* out = d_h + (size_t)p * WW;
    #pragma unroll
    for (int w = 0; w < WW; w++)
        out[w] = a*iw[w] + b*iw[WW + w] + ib[w];
}

// ---------------- rfft along y per (b,x) row (run once at start) --------------
__global__ void k_rfft_y() {
    extern __shared__ float2 sm[];
    float2* bufA = sm;
    float2* bufB = sm + 128*WW;
    __shared__ float2 tw[128];
    int tid = threadIdx.x;
    if (tid < 128) tw[tid] = d_tw[tid];
    int row = blockIdx.x;
    const float* hsrc = d_h + (size_t)row * YY * WW;
    for (int i = tid; i < YY*WW; i += 512) bufA[i] = make_float2(hsrc[i], 0.0f);
    __syncthreads();
    float2* R = fft128r4<WW,false,512>(bufA, bufB, tid, tw);
    float2* outhf = d_hf + (size_t)row * YHH * WW;
    for (int i = tid; i < YHH*WW; i += 512) outhf[i] = R[i];
}

// ---------------- fused fft-x + spectral matmul + ifft-x ----------------------
// block = (yh, batch-half of 4). L = 4*24 = 96 lines, smem = 2*128*96*8 = 192KB
__global__ __launch_bounds__(512) void k_spectral(int layer) {
    extern __shared__ float2 sm[];
    float2* bufA = sm;
    float2* bufB = sm + 128*96;
    __shared__ float2 tw[128];
    int tid = threadIdx.x;
    if (tid < 128) tw[tid] = d_tw[tid];
    int yh = blockIdx.x % YHH;
    int b0 = (blockIdx.x / YHH) * 4;

    // load hf lines: vectorized float4 (2 complex per load)
    {
        float4* bufA4 = (float4*)bufA;
        const float4* hf4 = (const float4*)d_hf;
        #pragma unroll 2
        for (int idx = tid; idx < 128*48; idx += 512) {
            int x = idx / 48, l = idx % 48;       // l = (b_local*24 + i)/2 pairs
            int b = b0 + l / 12, ip = l % 12;
            bufA4[x*48 + l] = hf4[(((size_t)b*XX + x)*YHH + yh)*12 + ip];
        }
    }
    __syncthreads();

    float2* F = fft128r4<96,false,512>(bufA, bufB, tid, tw);     // = bufA
    float2* G = (F == bufA) ? bufB : bufA;

    // yf[b][o] = sum_i hf[b][i] * w[i][o]; 4 batches per weight load
    const float2* wt = d_wt + (size_t)layer * NFREQ * IOSZ;
    #pragma unroll 2
    for (int j = tid; j < 128*WW; j += 512) {
        int x = j / WW, o = j % WW;
        const float2* wp  = wt + ((size_t)x*YHH + yh)*IOSZ + o;
        const float2* hp  = F + x*96;
        float2 a0 = {0,0}, a1 = {0,0}, a2 = {0,0}, a3 = {0,0};
        #pragma unroll
        for (int i = 0; i < WW; i++) {
            float2 w = __ldg(wp + i*WW);
            float2 h0 = hp[i], h1 = hp[24+i], h2 = hp[48+i], h3 = hp[72+i];
            a0.x += h0.x*w.x - h0.y*w.y;  a0.y += h0.x*w.y + h0.y*w.x;
            a1.x += h1.x*w.x - h1.y*w.y;  a1.y += h1.x*w.y + h1.y*w.x;
            a2.x += h2.x*w.x - h2.y*w.y;  a2.y += h2.x*w.y + h2.y*w.x;
            a3.x += h3.x*w.x - h3.y*w.y;  a3.y += h3.x*w.y + h3.y*w.x;
        }
        G[x*96      + o] = a0;
        G[x*96 + 24 + o] = a1;
        G[x*96 + 48 + o] = a2;
        G[x*96 + 72 + o] = a3;
    }
    __syncthreads();

    float2* S = fft128r4<96,true,512>(G, F, tid, tw);            // = G

    {
        const float4* S4 = (const float4*)S;
        float4* sp4 = (float4*)d_spec;
        #pragma unroll 2
        for (int idx = tid; idx < 128*48; idx += 512) {
            int x = idx / 48, l = idx % 48;
            int b = b0 + l / 12, ip = l % 12;
            sp4[(((size_t)b*XX + x)*YHH + yh)*12 + ip] = S4[x*48 + l];
        }
    }
}

// ---------------- fused irfft-y + 1x1 conv + relu (+ out-map) (+ next rfft-y) -
__global__ __launch_bounds__(512) void k_update(int layer, int t, int Trt, int flags,
                         const float* __restrict__ conv_w,
                         const float* __restrict__ conv_b,
                         const float* __restrict__ out_w,
                         const float* __restrict__ out_b,
                         float* __restrict__ outp) {
    extern __shared__ float2 sm[];
    float2* bufA = sm;
    float2* bufB = sm + 128*WW;
    __shared__ float2 tw[128];
    int tid = threadIdx.x;
    if (tid < 128) tw[tid] = d_tw[tid];
    int row = blockIdx.x;                 // b*128 + x

    // load half-spectrum (65 bins), Hermitian-extend to 128
    {
        const float4* spec4 = (const float4*)(d_spec + (size_t)row * YHH * WW);
        float4* bufA4 = (float4*)bufA;
        for (int i = tid; i < YHH*12; i += 512) bufA4[i] = spec4[i];
    }
    __syncthreads();
    for (int idx = tid; idx < 63*WW; idx += 512) {
        int p = 65 + idx / WW, ch = idx % WW;
        float2 v = bufA[(128 - p)*WW + ch];
        bufA[p*WW + ch] = make_float2(v.x, -v.y);
    }
    __syncthreads();

    float2* R = fft128r4<WW,true,512>(bufA, bufB, tid, tw);   // x1*16384 in .x
    float*  hrow = (float*)((R == bufA) ? bufB : bufA);

    {
        const float4* hsrc4 = (const float4*)(d_h + (size_t)row * YY * WW);
        float4* hrow4 = (float4*)hrow;
        for (int i = tid; i < YY*WW/4; i += 512) hrow4[i] = hsrc4[i];
    }
    __syncthreads();

    const float* cw = conv_w + layer * IOSZ;
    const float* cb = conv_b + layer * WW;
    float* hdst = d_h + (size_t)row * YY * WW;
    #pragma unroll 2
    for (int idx = tid; idx < YY*WW; idx += 512) {
        int y = idx / WW, o = idx % WW;
        float x1 = R[idx].x * (1.0f/16384.0f);
        float acc = cb[o];
        const float* hr = hrow + y*WW;
        #pragma unroll
        for (int i = 0; i < WW; i++) acc += hr[i] * __ldg(cw + i*WW + o);
        float hn = fmaxf(x1, 0.0f) + acc;
        hdst[idx] = hn;
        R[idx] = make_float2(hn, 0.0f);
    }
    __syncthreads();

    if (flags & 1) {   // out mapping for this timestep (COUT = 1)
        int b = row >> 7, xs = row & 127;
        float ob0 = out_b[0];
        for (int y = tid; y < YY; y += 512) {
            float s = ob0;
            #pragma unroll
            for (int o = 0; o < WW; o++) s += R[y*WW + o].x * __ldg(out_w + o);
            outp[(((size_t)b*Trt + t)*XX + xs)*YY + y] = s;
        }
    }

    if (flags & 2) {   // rfft-y of h_new for the next layer/timestep
        float2* other = (R == bufA) ? bufB : bufA;
        float2* HF = fft128r4<WW,false,512>(R, other, tid, tw);   // = R
        float4* outhf4 = (float4*)(d_hf + (size_t)row * YHH * WW);
        const float4* HF4 = (const float4*)HF;
        for (int i = tid; i < YHH*12; i += 512) outhf4[i] = HF4[i];
    }
}

// ---------------- host launcher ----------------------------------------------
extern "C" void kernel_launch(void* const* d_in, const int* in_sizes, int n_in,
                              void* d_out, int out_size) {
    const float* x      = (const float*)d_in[0];
    const float* in_w   = (const float*)d_in[1];
    const float* in_b   = (const float*)d_in[2];
    const float* spec_w = (const float*)d_in[3];
    const float* conv_w = (const float*)d_in[4];
    const float* conv_b = (const float*)d_in[5];
    const float* out_w  = (const float*)d_in[6];
    const float* out_b  = (const float*)d_in[7];
    float* outp = (float*)d_out;
    int Trt = out_size / (BB * XX * YY);

    const int SMEM_ROW  = 2 * 128 * WW * (int)sizeof(float2);   // 49152
    const int SMEM_SPEC = 2 * 128 * 96 * (int)sizeof(float2);   // 196608
    cudaFuncSetAttribute(k_spectral, cudaFuncAttributeMaxDynamicSharedMemorySize, SMEM_SPEC);
    cudaFuncSetAttribute(k_rfft_y,   cudaFuncAttributeMaxDynamicSharedMemorySize, SMEM_ROW);
    cudaFuncSetAttribute(k_update,   cudaFuncAttributeMaxDynamicSharedMemorySize, SMEM_ROW);

    k_twiddle<<<1, 128>>>();

    dim3 tb(32, 8), tg(NFREQ/32, IOSZ/32, DD);
    k_transpose<<<tg, tb>>>((const float2*)spec_w);

    k_inmap<<<(NPIX + 255)/256, 256>>>(x, in_w, in_b);
    k_rfft_y<<<NROWS, 512, SMEM_ROW>>>();

    for (int t = 0; t < Trt; t++) {
        for (int d = 0; d < DD; d++) {
            k_spectral<<<2*YHH, 512, SMEM_SPEC>>>(d);
            int flags = (d == DD-1 ? 1 : 0)
                      | ((t == Trt-1 && d == DD-1) ? 0 : 2);
            k_update<<<NROWS, 512, SMEM_ROW>>>(d, t, Trt, flags,
                                               conv_w, conv_b, out_w, out_b, outp);
        }
    }
}

// round 4
// speedup vs baseline: 1.4963x; 1.1750x over previous
#include <cuda_runtime.h>
#include <math.h>

#define BB 8
#define XX 128
#define YY 128
#define WW 24
#define DD 4
#define YHH 65
#define NPIX (BB*XX*YY)        // 131072
#define NROWS (BB*XX)          // 1024
#define NFREQ (XX*YHH)         // 8320
#define IOSZ (WW*WW)           // 576

// ---------------- device scratch (static: no allocations allowed) ------------
__device__ float  d_h[(size_t)NPIX*WW];             // (B,X,Y,W)      12.6 MB
__device__ float2 d_hf[(size_t)NROWS*YHH*WW];       // (B,X,YH,W)     12.8 MB
__device__ float2 d_spec[(size_t)NROWS*YHH*WW];     // (B,X,YH,W)     12.8 MB
__device__ float2 d_wt[(size_t)DD*NFREQ*IOSZ];      // (D,f,i,o)     153.4 MB
__device__ float2 d_tw[128];                        // exp(-i*pi*k/64)

__device__ __forceinline__ float2 cmulf(float2 a, float2 b) {
    return make_float2(a.x*b.x - a.y*b.y, a.x*b.y + a.y*b.x);
}

// ---------------- twiddle table ----------------------------------------------
__global__ void k_twiddle() {
    int k = threadIdx.x;
    double s, c;
    sincospi(-(double)k / 64.0, &s, &c);
    d_tw[k] = make_float2((float)c, (float)s);
}

// ---------------- weight transpose: (d, io, f) -> (d, f, io) ------------------
__global__ void k_transpose(const float2* __restrict__ src) {
    __shared__ float2 tile[32][33];
    int dd  = blockIdx.z;
    int f0  = blockIdx.x * 32;
    int io0 = blockIdx.y * 32;
    const float2* s = src + (size_t)dd * IOSZ * NFREQ;
    #pragma unroll
    for (int j = 0; j < 4; j++) {
        int io = io0 + threadIdx.y + j*8;
        int f  = f0 + threadIdx.x;
        tile[threadIdx.y + j*8][threadIdx.x] = s[(size_t)io * NFREQ + f];
    }
    __syncthreads();
    float2* dst = d_wt + (size_t)dd * NFREQ * IOSZ;
    #pragma unroll
    for (int j = 0; j < 4; j++) {
        int f  = f0 + threadIdx.y + j*8;
        int io = io0 + threadIdx.x;
        dst[(size_t)f * IOSZ + io] = tile[threadIdx.x][threadIdx.y + j*8];
    }
}

// ---------------- 128-point Stockham FFT, radix-4 x3 + radix-2 ----------------
template<int L, bool INV, int NT>
__device__ __forceinline__ float2* fft128r4(float2* p0, float2* p1, int tid,
                                            const float2* __restrict__ tw) {
    float2* src = p0; float2* dst = p1;
    #pragma unroll
    for (int st = 0; st < 3; st++) {
        const int s = 1 << (2*st);            // 1,4,16
        const int m = 32 >> (2*st);           // 32,8,2
        #pragma unroll 2
        for (int idx = tid; idx < 32*L; idx += NT) {
            int line = idx % L;
            int bf   = idx / L;
            int q = bf & (s - 1);
            int p = bf >> (2*st);
            int base = q + s*p;
            float2 a = src[ base          *L + line];
            float2 b = src[(base +   s*m)*L + line];
            float2 c = src[(base + 2*s*m)*L + line];
            float2 d = src[(base + 3*s*m)*L + line];
            float2 w1 = tw[p*s], w2 = tw[2*p*s], w3 = tw[3*p*s];
            if (INV) { w1.y = -w1.y; w2.y = -w2.y; w3.y = -w3.y; }
            float2 apc = make_float2(a.x+c.x, a.y+c.y);
            float2 amc = make_float2(a.x-c.x, a.y-c.y);
            float2 bpd = make_float2(b.x+d.x, b.y+d.y);
            float2 bmd = make_float2(b.x-d.x, b.y-d.y);
            float2 jb  = INV ? make_float2( bmd.y, -bmd.x)
                             : make_float2(-bmd.y,  bmd.x);
            int ob = q + 4*s*p;
            dst[ ob        *L + line] = make_float2(apc.x+bpd.x, apc.y+bpd.y);
            dst[(ob +   s)*L + line] = cmulf(w1, make_float2(amc.x-jb.x, amc.y-jb.y));
            dst[(ob + 2*s)*L + line] = cmulf(w2, make_float2(apc.x-bpd.x, apc.y-bpd.y));
            dst[(ob + 3*s)*L + line] = cmulf(w3, make_float2(amc.x+jb.x, amc.y+jb.y));
        }
        __syncthreads();
        float2* t = src; src = dst; dst = t;
    }
    #pragma unroll 2
    for (int idx = tid; idx < 64*L; idx += NT) {
        int line = idx % L;
        int q    = idx / L;
        float2 a = src[ q      *L + line];
        float2 b = src[(q + 64)*L + line];
        dst[ q      *L + line] = make_float2(a.x+b.x, a.y+b.y);
        dst[(q + 64)*L + line] = make_float2(a.x-b.x, a.y-b.y);
    }
    __syncthreads();
    return dst;   // == p0
}

// ---------------- in mapping ---------------------------------------------------
__global__ void k_inmap(const float* __restrict__ x,
                        const float* __restrict__ iw,
                        const float* __restrict__ ib) {
    int p = blockIdx.x * blockDim.x + threadIdx.x;
    if (p >= NPIX) return;
    float a = x[2*p], b = x[2*p + 1];
    float* out = d_h + (size_t)p * WW;
    #pragma unroll
    for (int w = 0; w < WW; w++)
        out[w] = a*iw[w] + b*iw[WW + w] + ib[w];
}

// ---------------- rfft along y per (b,x) row (runs once) ----------------------
__global__ void k_rfft_y() {
    extern __shared__ float2 sm[];
    float2* bufA = sm;
    float2* bufB = sm + 128*WW;
    __shared__ float2 tw[128];
    int tid = threadIdx.x;
    if (tid < 128) tw[tid] = d_tw[tid];
    int row = blockIdx.x;
    const float* hsrc = d_h + (size_t)row * YY * WW;
    for (int i = tid; i < YY*WW; i += 512) bufA[i] = make_float2(hsrc[i], 0.0f);
    __syncthreads();
    float2* R = fft128r4<WW,false,512>(bufA, bufB, tid, tw);
    float2* outhf = d_hf + (size_t)row * YHH * WW;
    for (int i = tid; i < YHH*WW; i += 512) outhf[i] = R[i];
}

// ---------------- fused fft-x + spectral matmul + ifft-x ----------------------
// block = (yh, batch-pair of 2). L = 2*24 = 48 lines, smem = 2*128*48*8 = 96KB
// grid yh-major: same-yh blocks adjacent -> weight L2 reuse.
__global__ __launch_bounds__(512) void k_spectral(int layer) {
    extern __shared__ float2 sm[];
    float2* bufA = sm;
    float2* bufB = sm + 128*48;
    __shared__ float2 tw[128];
    int tid = threadIdx.x;
    if (tid < 128) tw[tid] = d_tw[tid];
    int yh = blockIdx.x >> 2;
    int b0 = (blockIdx.x & 3) * 2;

    // load hf lines (float4 = 2 complex)
    {
        float4* bufA4 = (float4*)bufA;
        const float4* hf4 = (const float4*)d_hf;
        #pragma unroll 2
        for (int idx = tid; idx < 128*24; idx += 512) {
            int x = idx / 24, l = idx % 24;
            int b = b0 + l / 12, ip = l % 12;
            bufA4[x*24 + l] = hf4[(((size_t)b*XX + x)*YHH + yh)*12 + ip];
        }
    }
    __syncthreads();

    float2* F = fft128r4<48,false,512>(bufA, bufB, tid, tw);     // = bufA
    float2* G = (F == bufA) ? bufB : bufA;

    // yf[b][o] = sum_i hf[b][i] * w[i][o]; 2 batches x 2 outputs per thread-j
    const float2* wt = d_wt + (size_t)layer * NFREQ * IOSZ;
    #pragma unroll 2
    for (int j = tid; j < 128*12; j += 512) {
        int x = j / 12, op = j % 12, o = op * 2;
        const float4* wp4 = (const float4*)(wt + ((size_t)x*YHH + yh)*IOSZ + o);
        const float2* hp  = F + x*48;
        float2 a00 = {0,0}, a01 = {0,0}, a10 = {0,0}, a11 = {0,0};
        #pragma unroll
        for (int i = 0; i < WW; i++) {
            float4 w4 = __ldg(wp4 + i*12);           // w[i][o], w[i][o+1]
            float2 w0 = make_float2(w4.x, w4.y);
            float2 w1 = make_float2(w4.z, w4.w);
            float2 h0 = hp[i], h1 = hp[24+i];
            a00.x += h0.x*w0.x - h0.y*w0.y;  a00.y += h0.x*w0.y + h0.y*w0.x;
            a01.x += h0.x*w1.x - h0.y*w1.y;  a01.y += h0.x*w1.y + h0.y*w1.x;
            a10.x += h1.x*w0.x - h1.y*w0.y;  a10.y += h1.x*w0.y + h1.y*w0.x;
            a11.x += h1.x*w1.x - h1.y*w1.y;  a11.y += h1.x*w1.y + h1.y*w1.x;
        }
        float4* G4 = (float4*)G;
        G4[(x*48 + o) >> 1]      = make_float4(a00.x, a00.y, a01.x, a01.y);
        G4[(x*48 + 24 + o) >> 1] = make_float4(a10.x, a10.y, a11.x, a11.y);
    }
    __syncthreads();

    float2* S = fft128r4<48,true,512>(G, F, tid, tw);            // = G

    {
        const float4* S4 = (const float4*)S;
        float4* sp4 = (float4*)d_spec;
        #pragma unroll 2
        for (int idx = tid; idx < 128*24; idx += 512) {
            int x = idx / 24, l = idx % 24;
            int b = b0 + l / 12, ip = l % 12;
            sp4[(((size_t)b*XX + x)*YHH + yh)*12 + ip] = S4[x*24 + l];
        }
    }
}

// ---------------- fused irfft-y + 1x1 conv + relu (+ out-map) (+ next rfft-y) -
// Channel-pair packing: 12 complex lines carry 24 real channels through both
// the inverse and forward y-FFTs.
// irfft semantics: imaginary parts of DC (k=0) and Nyquist (k=64) bins are
// IGNORED — they must be zeroed during packing or they contaminate the pair.
__global__ __launch_bounds__(512) void k_update(int layer, int t, int Trt, int flags,
                         const float* __restrict__ conv_w,
                         const float* __restrict__ conv_b,
                         const float* __restrict__ out_w,
                         const float* __restrict__ out_b,
                         float* __restrict__ outp) {
    extern __shared__ float2 sm[];
    float2* A  = sm;                      // 128*12 complex
    float2* Bb = sm + 128*12;
    float*  hrow = (float*)(sm + 2*128*12);   // 128*24 floats
    __shared__ float2 tw[128];
    int tid = threadIdx.x;
    if (tid < 128) tw[tid] = d_tw[tid];
    int row = blockIdx.x;                 // b*128 + x

    // load previous h (for 1x1 conv) — independent stream, issue first
    {
        const float4* hsrc4 = (const float4*)(d_h + (size_t)row * YY * WW);
        float4* hrow4 = (float4*)hrow;
        for (int i = tid; i < YY*WW/4; i += 512) hrow4[i] = hsrc4[i];
    }

    // pack Z[k] = A[k] + i*B[k] with Hermitian extension folded in;
    // DC/Nyquist imaginary parts dropped (irfft ignores them).
    {
        const float4* spec4 = (const float4*)(d_spec + (size_t)row * YHH * WW);
        #pragma unroll 2
        for (int idx = tid; idx < 128*12; idx += 512) {
            int k = idx / 12, c = idx % 12;
            float4 v;
            float2 Zv;
            if (k == 0 || k == 64) {
                v = spec4[k*12 + c];
                Zv = make_float2(v.x, v.z);          // Re(A) + i*Re(B)
            } else if (k < 64) {
                v = spec4[k*12 + c];                 // (A.x,A.y,B.x,B.y)
                Zv = make_float2(v.x - v.w, v.y + v.z);
            } else {
                v = spec4[(128 - k)*12 + c];
                Zv = make_float2(v.x + v.w, v.z - v.y);
            }
            A[k*12 + c] = Zv;
        }
    }
    __syncthreads();

    float2* R = fft128r4<12,true,512>(A, Bb, tid, tw);   // = A; z = a + i*b (x16384)

    // conv + relu; write packed h_new pairs into Bb
    const float* cw = conv_w + layer * IOSZ;
    const float* cb = conv_b + layer * WW;
    float2* hdst2 = (float2*)(d_h + (size_t)row * YY * WW);
    #pragma unroll 2
    for (int idx = tid; idx < 128*12; idx += 512) {
        int y = idx / 12, c = idx % 12, o = c*2;
        float2 z = R[idx];
        float acc0 = cb[o], acc1 = cb[o+1];
        const float* hr = hrow + y*WW;
        #pragma unroll
        for (int i = 0; i < WW; i++) {
            float hv = hr[i];
            float2 w = __ldg((const float2*)(cw + i*WW + o));
            acc0 += hv * w.x;
            acc1 += hv * w.y;
        }
        float hn0 = fmaxf(z.x * (1.0f/16384.0f), 0.0f) + acc0;
        float hn1 = fmaxf(z.y * (1.0f/16384.0f), 0.0f) + acc1;
        Bb[idx] = make_float2(hn0, hn1);
        hdst2[y*12 + c] = make_float2(hn0, hn1);
    }
    __syncthreads();

    if (flags & 1) {   // out mapping (COUT = 1)
        int b = row >> 7, xs = row & 127;
        float ob0 = out_b[0];
        for (int y = tid; y < YY; y += 512) {
            float s = ob0;
            #pragma unroll
            for (int c = 0; c < 12; c++) {
                float2 z = Bb[y*12 + c];
                s += z.x * __ldg(out_w + 2*c) + z.y * __ldg(out_w + 2*c + 1);
            }
            outp[(((size_t)b*Trt + t)*XX + xs)*YY + y] = s;
        }
    }

    if (flags & 2) {   // forward rfft-y of packed h_new, then unscramble
        float2* Z = fft128r4<12,false,512>(Bb, A, tid, tw);   // = Bb
        float4* hf4 = (float4*)(d_hf + (size_t)row * YHH * WW);
        #pragma unroll 2
        for (int idx = tid; idx < YHH*12; idx += 512) {
            int k = idx / 12, c = idx % 12;
            float2 Zk = Z[k*12 + c];
            float2 Zm = Z[((128 - k) & 127)*12 + c];
            // A = (Z[k] + conj(Z[-k]))/2 ; B = (Z[k] - conj(Z[-k]))/(2i)
            float ax = 0.5f*(Zk.x + Zm.x), ay = 0.5f*(Zk.y - Zm.y);
            float bx = 0.5f*(Zk.y + Zm.y), by = 0.5f*(Zm.x - Zk.x);
            hf4[k*12 + c] = make_float4(ax, ay, bx, by);
        }
    }
}

// ---------------- host launcher ----------------------------------------------
extern "C" void kernel_launch(void* const* d_in, const int* in_sizes, int n_in,
                              void* d_out, int out_size) {
    const float* x      = (const float*)d_in[0];
    const float* in_w   = (const float*)d_in[1];
    const float* in_b   = (const float*)d_in[2];
    const float* spec_w = (const float*)d_in[3];
    const float* conv_w = (const float*)d_in[4];
    const float* conv_b = (const float*)d_in[5];
    const float* out_w  = (const float*)d_in[6];
    const float* out_b  = (const float*)d_in[7];
    float* outp = (float*)d_out;
    int Trt = out_size / (BB * XX * YY);

    const int SMEM_ROW  = 2 * 128 * WW * (int)sizeof(float2);     // 49152
    const int SMEM_SPEC = 2 * 128 * 48 * (int)sizeof(float2);     // 98304
    const int SMEM_UPD  = 2 * 128 * 12 * (int)sizeof(float2)
                        + 128 * WW * (int)sizeof(float);          // 36864
    cudaFuncSetAttribute(k_spectral, cudaFuncAttributeMaxDynamicSharedMemorySize, SMEM_SPEC);
    cudaFuncSetAttribute(k_rfft_y,   cudaFuncAttributeMaxDynamicSharedMemorySize, SMEM_ROW);
    cudaFuncSetAttribute(k_update,   cudaFuncAttributeMaxDynamicSharedMemorySize, SMEM_UPD);

    k_twiddle<<<1, 128>>>();

    dim3 tb(32, 8), tg(NFREQ/32, IOSZ/32, DD);
    k_transpose<<<tg, tb>>>((const float2*)spec_w);

    k_inmap<<<(NPIX + 255)/256, 256>>>(x, in_w, in_b);
    k_rfft_y<<<NROWS, 512, SMEM_ROW>>>();

    for (int t = 0; t < Trt; t++) {
        for (int d = 0; d < DD; d++) {
            k_spectral<<<4*YHH, 512, SMEM_SPEC>>>(d);
            int flags = (d == DD-1 ? 1 : 0)
                      | ((t == Trt-1 && d == DD-1) ? 0 : 2);
            k_update<<<NROWS, 512, SMEM_UPD>>>(d, t, Trt, flags,
                                               conv_w, conv_b, out_w, out_b, outp);
        }
    }
}

// round 6
// speedup vs baseline: 1.9825x; 1.3250x over previous
#include <cuda_runtime.h>
#include <math.h>

#define BB 8
#define XX 128
#define YY 128
#define WW 24
#define DD 4
#define YHH 65
#define NPIX (BB*XX*YY)        // 131072
#define NROWS (BB*XX)          // 1024
#define NFREQ (XX*YHH)         // 8320
#define IOSZ (WW*WW)           // 576

// ---------------- device scratch (static: no allocations allowed) ------------
__device__ float  d_h[(size_t)NPIX*WW];             // (B,X,Y,W)      12.6 MB
__device__ float2 d_hf[(size_t)NROWS*YHH*WW];       // (B,X,YH,W)     12.8 MB
__device__ float2 d_spec[(size_t)NROWS*YHH*WW];     // (B,X,YH,W)     12.8 MB
__device__ float2 d_wt[(size_t)DD*NFREQ*IOSZ];      // (D,f,i,o)     153.4 MB
__device__ float2 d_tw[128];                        // exp(-i*pi*k/64)

__device__ __forceinline__ float4 cmul4(float4 v, float2 w) {
    return make_float4(v.x*w.x - v.y*w.y, v.x*w.y + v.y*w.x,
                       v.z*w.x - v.w*w.y, v.z*w.y + v.w*w.x);
}
__device__ __forceinline__ float4 add4(float4 a, float4 b) {
    return make_float4(a.x+b.x, a.y+b.y, a.z+b.z, a.w+b.w);
}
__device__ __forceinline__ float4 sub4(float4 a, float4 b) {
    return make_float4(a.x-b.x, a.y-b.y, a.z-b.z, a.w-b.w);
}
// fwd: multiply both packed complex by -j ; inv: by +j
template<bool INV>
__device__ __forceinline__ float4 mulj4(float4 v) {
    return INV ? make_float4(-v.y, v.x, -v.w, v.z)
               : make_float4( v.y,-v.x,  v.w,-v.z);
}

// ---------------- twiddle table ----------------------------------------------
__global__ void k_twiddle() {
    int k = threadIdx.x;
    double s, c;
    sincospi(-(double)k / 64.0, &s, &c);
    d_tw[k] = make_float2((float)c, (float)s);
}

// ---------------- weight transpose: (d, io, f) -> (d, f, io) ------------------
__global__ void k_transpose(const float2* __restrict__ src) {
    __shared__ float2 tile[32][33];
    int dd  = blockIdx.z;
    int f0  = blockIdx.x * 32;
    int io0 = blockIdx.y * 32;
    const float2* s = src + (size_t)dd * IOSZ * NFREQ;
    #pragma unroll
    for (int j = 0; j < 4; j++) {
        int io = io0 + threadIdx.y + j*8;
        int f  = f0 + threadIdx.x;
        tile[threadIdx.y + j*8][threadIdx.x] = s[(size_t)io * NFREQ + f];
    }
    __syncthreads();
    float2* dst = d_wt + (size_t)dd * NFREQ * IOSZ;
    #pragma unroll
    for (int j = 0; j < 4; j++) {
        int f  = f0 + threadIdx.y + j*8;
        int io = io0 + threadIdx.x;
        dst[(size_t)f * IOSZ + io] = tile[threadIdx.x][threadIdx.y + j*8];
    }
}

// ---------------- 128-point Stockham FFT, radix 4*4*8, float4 lanes -----------
// LP = line-pairs (2 complex per float4). Layout: buf[point*LP + lp].
// 3 stages, 3 syncs. Result ends in p1 (returned). Ends with __syncthreads().
template<int LP, bool INV, int NT>
__device__ __forceinline__ float4* fft128(float4* p0, float4* p1, int tid,
                                          const float2* __restrict__ tw) {
    float4* src = p0; float4* dst = p1;
    // -------- two radix-4 stages: (s=1,m=32) then (s=4,m=8) --------
    #pragma unroll
    for (int st = 0; st < 2; st++) {
        const int s = (st == 0) ? 1 : 4;
        const int m = (st == 0) ? 32 : 8;
        #pragma unroll 2
        for (int idx = tid; idx < 32*LP; idx += NT) {
            int lp = idx % LP;
            int bf = idx / LP;
            int q = bf & (s - 1);
            int p = bf >> (2*st);
            int base = q + s*p;
            float4 a = src[ base          *LP + lp];
            float4 b = src[(base +   s*m)*LP + lp];
            float4 c = src[(base + 2*s*m)*LP + lp];
            float4 d = src[(base + 3*s*m)*LP + lp];
            float2 w1 = tw[p*s], w2 = tw[2*p*s], w3 = tw[3*p*s];
            if (INV) { w1.y = -w1.y; w2.y = -w2.y; w3.y = -w3.y; }
            float4 apc = add4(a, c), amc = sub4(a, c);
            float4 bpd = add4(b, d), bmd = sub4(b, d);
            float4 jb  = mulj4<INV>(bmd);          // -j*bmd (fwd) / +j*bmd (inv)
            int ob = q + 4*s*p;
            dst[ ob        *LP + lp] = add4(apc, bpd);
            dst[(ob +   s)*LP + lp] = cmul4(add4(amc, jb), w1);
            dst[(ob + 2*s)*LP + lp] = cmul4(sub4(apc, bpd), w2);
            dst[(ob + 3*s)*LP + lp] = cmul4(sub4(amc, jb), w3);
        }
        __syncthreads();
        float4* t = src; src = dst; dst = t;
    }
    // -------- final radix-8 stage: s=16, p=0 (no table twiddles) --------
    const float C = 0.70710678118654752f;
    #pragma unroll 2
    for (int idx = tid; idx < 16*LP; idx += NT) {
        int lp = idx % LP;
        int q  = idx / LP;                 // 0..15
        float4 x0 = src[(q       )*LP + lp];
        float4 x1 = src[(q + 16 )*LP + lp];
        float4 x2 = src[(q + 32 )*LP + lp];
        float4 x3 = src[(q + 48 )*LP + lp];
        float4 x4 = src[(q + 64 )*LP + lp];
        float4 x5 = src[(q + 80 )*LP + lp];
        float4 x6 = src[(q + 96 )*LP + lp];
        float4 x7 = src[(q + 112)*LP + lp];
        // FFT4 of evens (x0,x2,x4,x6)
        float4 t0 = add4(x0, x4), t1 = sub4(x0, x4);
        float4 t2 = add4(x2, x6), t3 = sub4(x2, x6);
        float4 jt3 = mulj4<INV>(t3);
        float4 e0 = add4(t0, t2), e2 = sub4(t0, t2);
        float4 e1 = add4(t1, jt3), e3 = sub4(t1, jt3);
        // FFT4 of odds (x1,x3,x5,x7)
        float4 u0 = add4(x1, x5), u1 = sub4(x1, x5);
        float4 u2 = add4(x3, x7), u3 = sub4(x3, x7);
        float4 ju3 = mulj4<INV>(u3);
        float4 o0 = add4(u0, u2), o2 = sub4(u0, u2);
        float4 o1 = add4(u1, ju3), o3 = sub4(u1, ju3);
        // apply w8^r to odd outputs
        float2 w81 = INV ? make_float2( C,  C) : make_float2( C, -C);
        float2 w83 = INV ? make_float2(-C,  C) : make_float2(-C, -C);
        float4 o1w = cmul4(o1, w81);
        float4 o2w = mulj4<INV>(o2);
        float4 o3w = cmul4(o3, w83);
        dst[(q       )*LP + lp] = add4(e0, o0);
        dst[(q + 16 )*LP + lp] = add4(e1, o1w);
        dst[(q + 32 )*LP + lp] = add4(e2, o2w);
        dst[(q + 48 )*LP + lp] = add4(e3, o3w);
        dst[(q + 64 )*LP + lp] = sub4(e0, o0);
        dst[(q + 80 )*LP + lp] = sub4(e1, o1w);
        dst[(q + 96 )*LP + lp] = sub4(e2, o2w);
        dst[(q + 112)*LP + lp] = sub4(e3, o3w);
    }
    __syncthreads();
    return dst;    // == p1
}

// ---------------- in mapping ---------------------------------------------------
__global__ void k_inmap(const float* __restrict__ x,
                        const float* __restrict__ iw,
                        const float* __restrict__ ib) {
    int p = blockIdx.x * blockDim.x + threadIdx.x;
    if (p >= NPIX) return;
    float a = x[2*p], b = x[2*p + 1];
    float* out = d_h + (size_t)p * WW;
    #pragma unroll
    for (int w = 0; w < WW; w++)
        out[w] = a*iw[w] + b*iw[WW + w] + ib[w];
}

// ---------------- rfft along y per (b,x) row (runs once) ----------------------
__global__ void k_rfft_y() {
    extern __shared__ float4 sm4[];
    float4* bufA = sm4;                 // 128*12 float4 (24 complex lines)
    float4* bufB = sm4 + 128*12;
    __shared__ float2 tw[128];
    int tid = threadIdx.x;
    if (tid < 128) tw[tid] = d_tw[tid];
    int row = blockIdx.x;
    const float* hsrc = d_h + (size_t)row * YY * WW;
    float2* bufA2 = (float2*)bufA;
    for (int i = tid; i < YY*WW; i += 512) bufA2[i] = make_float2(hsrc[i], 0.0f);
    __syncthreads();
    float4* R = fft128<12,false,512>(bufA, bufB, tid, tw);
    float4* outhf = (float4*)(d_hf + (size_t)row * YHH * WW);
    for (int i = tid; i < YHH*12; i += 512) outhf[i] = R[i];
}

// ---------------- fused fft-x + spectral matmul + ifft-x ----------------------
// block = (yh, batch-pair of 2). 48 lines = 24 float4 lanes. smem 96KB, 2 CTA/SM
__global__ __launch_bounds__(512) void k_spectral(int layer) {
    extern __shared__ float4 sm4[];
    float4* bufA = sm4;                 // 128*24 float4
    float4* bufB = sm4 + 128*24;
    __shared__ float2 tw[128];
    int tid = threadIdx.x;
    if (tid < 128) tw[tid] = d_tw[tid];
    int yh = blockIdx.x >> 2;
    int b0 = (blockIdx.x & 3) * 2;

    // load hf lines (float4 = 2 complex)
    {
        const float4* hf4 = (const float4*)d_hf;
        #pragma unroll 2
        for (int idx = tid; idx < 128*24; idx += 512) {
            int x = idx / 24, l = idx % 24;
            int b = b0 + l / 12, ip = l % 12;
            bufA[x*24 + l] = hf4[(((size_t)b*XX + x)*YHH + yh)*12 + ip];
        }
    }
    __syncthreads();

    float4* F4 = fft128<24,false,512>(bufA, bufB, tid, tw);   // = bufB
    float4* G4 = (F4 == bufA) ? bufB : bufA;
    float2* F = (float2*)F4;

    // yf[b][o] = sum_i hf[b][i] * w[i][o]; 2 batches x 2 outputs per thread-j
    const float2* wt = d_wt + (size_t)layer * NFREQ * IOSZ;
    #pragma unroll 2
    for (int j = tid; j < 128*12; j += 512) {
        int x = j / 12, op = j % 12, o = op * 2;
        const float4* wp4 = (const float4*)(wt + ((size_t)x*YHH + yh)*IOSZ + o);
        const float2* hp  = F + x*48;
        float2 a00 = {0,0}, a01 = {0,0}, a10 = {0,0}, a11 = {0,0};
        #pragma unroll
        for (int i = 0; i < WW; i++) {
            float4 w4 = __ldg(wp4 + i*12);           // w[i][o], w[i][o+1]
            float2 w0 = make_float2(w4.x, w4.y);
            float2 w1 = make_float2(w4.z, w4.w);
            float2 h0 = hp[i], h1 = hp[24+i];
            a00.x += h0.x*w0.x - h0.y*w0.y;  a00.y += h0.x*w0.y + h0.y*w0.x;
            a01.x += h0.x*w1.x - h0.y*w1.y;  a01.y += h0.x*w1.y + h0.y*w1.x;
            a10.x += h1.x*w0.x - h1.y*w0.y;  a10.y += h1.x*w0.y + h1.y*w0.x;
            a11.x += h1.x*w1.x - h1.y*w1.y;  a11.y += h1.x*w1.y + h1.y*w1.x;
        }
        G4[(x*48 + o) >> 1]      = make_float4(a00.x, a00.y, a01.x, a01.y);
        G4[(x*48 + 24 + o) >> 1] = make_float4(a10.x, a10.y, a11.x, a11.y);
    }
    __syncthreads();

    float4* S = fft128<24,true,512>(G4, F4, tid, tw);   // = F4

    {
        float4* sp4 = (float4*)d_spec;
        #pragma unroll 2
        for (int idx = tid; idx < 128*24; idx += 512) {
            int x = idx / 24, l = idx % 24;
            int b = b0 + l / 12, ip = l % 12;
            sp4[(((size_t)b*XX + x)*YHH + yh)*12 + ip] = S[x*24 + l];
        }
    }
}

// ---------------- fused irfft-y + 1x1 conv + relu (+ out-map) (+ next rfft-y) -
// Channel-pair packing: 12 complex lines (= 6 float4 lanes) carry 24 channels.
// irfft semantics: DC/Nyquist imaginary parts are ignored -> zero them on pack.
__global__ __launch_bounds__(512) void k_update(int layer, int t, int Trt, int flags,
                         const float* __restrict__ conv_w,
                         const float* __restrict__ conv_b,
                         const float* __restrict__ out_w,
                         const float* __restrict__ out_b,
                         float* __restrict__ outp) {
    extern __shared__ float4 sm4[];
    float4* A4  = sm4;                        // 128*6 float4 = 12 complex lines
    float4* B4  = sm4 + 128*6;
    float*  hrow = (float*)(sm4 + 2*128*6);   // 128*24 floats
    float2* A  = (float2*)A4;
    __shared__ float2 tw[128];
    int tid = threadIdx.x;
    if (tid < 128) tw[tid] = d_tw[tid];
    int row = blockIdx.x;                 // b*128 + x

    // load previous h (for 1x1 conv) — independent stream, issue first
    {
        const float4* hsrc4 = (const float4*)(d_h + (size_t)row * YY * WW);
        float4* hrow4 = (float4*)hrow;
        for (int i = tid; i < YY*WW/4; i += 512) hrow4[i] = hsrc4[i];
    }

    // pack Z[k] = A[k] + i*B[k] with Hermitian extension folded in;
    // DC/Nyquist imaginary parts dropped (irfft ignores them).
    {
        const float4* spec4 = (const float4*)(d_spec + (size_t)row * YHH * WW);
        #pragma unroll 2
        for (int idx = tid; idx < 128*12; idx += 512) {
            int k = idx / 12, c = idx % 12;
            float4 v;
            float2 Zv;
            if (k == 0 || k == 64) {
                v = spec4[k*12 + c];
                Zv = make_float2(v.x, v.z);          // Re(A) + i*Re(B)
            } else if (k < 64) {
                v = spec4[k*12 + c];                 // (A.x,A.y,B.x,B.y)
                Zv = make_float2(v.x - v.w, v.y + v.z);
            } else {
                v = spec4[(128 - k)*12 + c];
                Zv = make_float2(v.x + v.w, v.z - v.y);
            }
            A[k*12 + c] = Zv;
        }
    }
    __syncthreads();

    float4* R4 = fft128<6,true,512>(A4, B4, tid, tw);    // = B4
    float2* R  = (float2*)R4;                            // z = a + i*b (x16384)
    float4* P4 = (R4 == A4) ? B4 : A4;                   // = A4
    float2* P  = (float2*)P4;

    // conv + relu; write packed h_new pairs into P
    const float* cw = conv_w + layer * IOSZ;
    const float* cb = conv_b + layer * WW;
    float2* hdst2 = (float2*)(d_h + (size_t)row * YY * WW);
    #pragma unroll 2
    for (int idx = tid; idx < 128*12; idx += 512) {
        int y = idx / 12, c = idx % 12, o = c*2;
        float2 z = R[idx];
        float acc0 = cb[o], acc1 = cb[o+1];
        const float* hr = hrow + y*WW;
        #pragma unroll
        for (int i = 0; i < WW; i++) {
            float hv = hr[i];
            float2 w = __ldg((const float2*)(cw + i*WW + o));
            acc0 += hv * w.x;
            acc1 += hv * w.y;
        }
        float hn0 = fmaxf(z.x * (1.0f/16384.0f), 0.0f) + acc0;
        float hn1 = fmaxf(z.y * (1.0f/16384.0f), 0.0f) + acc1;
        P[idx] = make_float2(hn0, hn1);
        hdst2[y*12 + c] = make_float2(hn0, hn1);
    }
    __syncthreads();

    if (flags & 1) {   // out mapping (COUT = 1) — reads P (h_new), before fwd FFT
        int b = row >> 7, xs = row & 127;
        float ob0 = out_b[0];
        for (int y = tid; y < YY; y += 512) {
            float s = ob0;
            #pragma unroll
            for (int c = 0; c < 12; c++) {
                float2 z = P[y*12 + c];
                s += z.x * __ldg(out_w + 2*c) + z.y * __ldg(out_w + 2*c + 1);
            }
            outp[(((size_t)b*Trt + t)*XX + xs)*YY + y] = s;
        }
    }

    if (flags & 2) {   // forward rfft-y of packed h_new, then unscramble
        float4* other = (P4 == A4) ? B4 : A4;
        float4* Z4 = fft128<6,false,512>(P4, other, tid, tw);
        float2* Z = (float2*)Z4;
        float4* hf4 = (float4*)(d_hf + (size_t)row * YHH * WW);
        #pragma unroll 2
        for (int idx = tid; idx < YHH*12; idx += 512) {
            int k = idx / 12, c = idx % 12;
            float2 Zk = Z[k*12 + c];
            float2 Zm = Z[((128 - k) & 127)*12 + c];
            // A = (Z[k] + conj(Z[-k]))/2 ; B = (Z[k] - conj(Z[-k]))/(2i)
            float ax = 0.5f*(Zk.x + Zm.x), ay = 0.5f*(Zk.y - Zm.y);
            float bx = 0.5f*(Zk.y + Zm.y), by = 0.5f*(Zm.x - Zk.x);
            hf4[k*12 + c] = make_float4(ax, ay, bx, by);
        }
    }
}

// ---------------- host launcher ----------------------------------------------
extern "C" void kernel_launch(void* const* d_in, const int* in_sizes, int n_in,
                              void* d_out, int out_size) {
    const float* x      = (const float*)d_in[0];
    const float* in_w   = (const float*)d_in[1];
    const float* in_b   = (const float*)d_in[2];
    const float* spec_w = (const float*)d_in[3];
    const float* conv_w = (const float*)d_in[4];
    const float* conv_b = (const float*)d_in[5];
    const float* out_w  = (const float*)d_in[6];
    const float* out_b  = (const float*)d_in[7];
    float* outp = (float*)d_out;
    int Trt = out_size / (BB * XX * YY);

    const int SMEM_ROW  = 2 * 128 * 12 * (int)sizeof(float4);     // 49152
    const int SMEM_SPEC = 2 * 128 * 24 * (int)sizeof(float4);     // 98304
    const int SMEM_UPD  = 2 * 128 * 6 * (int)sizeof(float4)
                        + 128 * WW * (int)sizeof(float);          // 36864
    cudaFuncSetAttribute(k_spectral, cudaFuncAttributeMaxDynamicSharedMemorySize, SMEM_SPEC);
    cudaFuncSetAttribute(k_rfft_y,   cudaFuncAttributeMaxDynamicSharedMemorySize, SMEM_ROW);
    cudaFuncSetAttribute(k_update,   cudaFuncAttributeMaxDynamicSharedMemorySize, SMEM_UPD);

    k_twiddle<<<1, 128>>>();

    dim3 tb(32, 8), tg(NFREQ/32, IOSZ/32, DD);
    k_transpose<<<tg, tb>>>((const float2*)spec_w);

    k_inmap<<<(NPIX + 255)/256, 256>>>(x, in_w, in_b);
    k_rfft_y<<<NROWS, 512, SMEM_ROW>>>();

    for (int t = 0; t < Trt; t++) {
        for (int d = 0; d < DD; d++) {
            k_spectral<<<4*YHH, 512, SMEM_SPEC>>>(d);
            int flags = (d == DD-1 ? 1 : 0)
                      | ((t == Trt-1 && d == DD-1) ? 0 : 2);
            k_update<<<NROWS, 512, SMEM_UPD>>>(d, t, Trt, flags,
                                               conv_w, conv_b, out_w, out_b, outp);
        }
    }
}